// round 16
// baseline (speedup 1.0000x reference)
#include <cuda_runtime.h>
#include <cuda_fp16.h>

#define IN_D 256
#define RU   128
#define OD   64
#define NB   2048
#define DDIM 32896
#define HCONST 0.5f
#define EPS_C  1e-8f
#define LN_EPS_C 1e-5f

typedef unsigned long long ull;

// ---------------- device scratch (allocation-free) ----------------
__device__ float    g_S  [IN_D*RU];
__device__ float    g_CS [IN_D*RU];
__device__ float    g_K2 [RU];
__device__ float    g_Gp [OD*9];       // G partials  [o][slot], race-free
__device__ float    g_Bp [OD*9];       // Bc partials [o][slot]
__device__ float    g_fsT[RU*NB];      // (frs*rstd) transposed: [r][b]
__device__ float    g_c0 [NB];         // -mu*rstd
__device__ float    g_Wt [OD*RU];      // tail weights gamma*W[o][32768+r]
__device__ unsigned g_Bh [256*4096];   // B fp16 [i=256][n_w=4096] f16x2, n_w = o*64 + r/2
__device__ unsigned g_Xh [NB*128];     // X fp16 [b][128 words]

// ---------------- helpers ----------------
__device__ __forceinline__ ull pk2(float x){
    unsigned u = __float_as_uint(x);
    ull r; asm("mov.b64 %0, {%1, %1};" : "=l"(r) : "r"(u)); return r;
}
__device__ __forceinline__ void fma2(ull &d, ull a, ull b){
    asm("fma.rn.f32x2 %0, %1, %2, %0;" : "+l"(d) : "l"(a), "l"(b));
}
__device__ __forceinline__ void unpk(ull v, float &lo, float &hi){
    unsigned ulo, uhi;
    asm("mov.b64 {%0, %1}, %2;" : "=r"(ulo), "=r"(uhi) : "l"(v));
    lo = __uint_as_float(ulo); hi = __uint_as_float(uhi);
}
__device__ __forceinline__ unsigned pack_h2(float a, float b){
    unsigned h; asm("cvt.rn.f16x2.f32 %0, %1, %2;" : "=r"(h) : "f"(b), "f"(a));
    return h;
}
__device__ __forceinline__ unsigned smem_u32(const void* p){
    unsigned a;
    asm("{ .reg .u64 t; cvta.to.shared.u64 t, %1; cvt.u32.u64 %0, t; }" : "=r"(a) : "l"(p));
    return a;
}
__device__ __forceinline__ void cpa16(unsigned dst, const void* src){
    asm volatile("cp.async.cg.shared.global [%0], [%1], 16;" :: "r"(dst), "l"(src) : "memory");
}
#define CPA_COMMIT() asm volatile("cp.async.commit_group;" ::: "memory")
#define CPA_WAIT2()  asm volatile("cp.async.wait_group 2;" ::: "memory")
#define CPA_WAIT1()  asm volatile("cp.async.wait_group 1;" ::: "memory")
#define CPA_WAIT0()  asm volatile("cp.async.wait_group 0;" ::: "memory")

__device__ __forceinline__ void ldm4(unsigned* r, unsigned addr){
    asm volatile("ldmatrix.sync.aligned.m8n8.x4.shared.b16 {%0,%1,%2,%3}, [%4];"
        : "=r"(r[0]), "=r"(r[1]), "=r"(r[2]), "=r"(r[3]) : "r"(addr));
}
__device__ __forceinline__ void ldm4t(unsigned* r, unsigned addr){
    asm volatile("ldmatrix.sync.aligned.m8n8.x4.trans.shared.b16 {%0,%1,%2,%3}, [%4];"
        : "=r"(r[0]), "=r"(r[1]), "=r"(r[2]), "=r"(r[3]) : "r"(addr));
}
__device__ __forceinline__ void mma16816(float* d, const unsigned* a, const unsigned* b){
    asm volatile("mma.sync.aligned.m16n8k16.row.col.f32.f16.f16.f32 "
        "{%0,%1,%2,%3}, {%4,%5,%6,%7}, {%8,%9}, {%0,%1,%2,%3};"
        : "+f"(d[0]), "+f"(d[1]), "+f"(d[2]), "+f"(d[3])
        : "r"(a[0]), "r"(a[1]), "r"(a[2]), "r"(a[3]), "r"(b[0]), "r"(b[1]));
}

// ---------------- launch 1: k0s — S/CS + K2 only (k1's dependencies) ----------------
__global__ void k0s_prep(const float* __restrict__ centers, const float* __restrict__ sigmas){
    __shared__ float red[256];
    int t = threadIdx.x, blk = blockIdx.x;
    if (blk < 128){
        int i = blk*256 + t;
        float sg = sigmas[i];
        float s  = HCONST/(sg*sg) + EPS_C;
        g_S[i]  = s;
        g_CS[i] = centers[i]*s;
    } else {
        int r = blk - 128;
        float c = centers[t*RU + r], sg = sigmas[t*RU + r];
        float s = HCONST/(sg*sg) + EPS_C;
        red[t] = c*c*s;
        __syncthreads();
        for (int s2 = 128; s2 > 0; s2 >>= 1){
            if (t < s2) red[t] += red[t+s2];
            __syncthreads();
        }
        if (t == 0) g_K2[r] = red[0];
    }
}

// ---------------- launch 2: k1w — k1 blocks [0,256) || W-slab blocks [256,768) || X pack [768,896) ----------------
// k1 and the k2-prep streaming co-run on one grid (no cross-block deps inside).
#define K1_SMEM 41984
__global__ __launch_bounds__(128,4) void k1w(const float* __restrict__ X,
                                             const float* __restrict__ W,
                                             const float* __restrict__ gamma,
                                             const float* __restrict__ beta){
    extern __shared__ float sm1[];
    __shared__ float K2s[RU];
    __shared__ float rg[4], rb[4], trg[4], trb[4];
    const int tid = threadIdx.x, blk = blockIdx.x;

    if (blk < 256){
        // ---- k1: firing levels + softmax + closed-form LN stats ----
        float* Xs = sm1;                 // [256][9]
        float* Sb = sm1 + 2304;          // 2 stages x [16][128]
        float* Cb = Sb  + 4096;
        const int b0   = blk * 8;
        const int lane = tid & 31, wg = tid >> 5;
        const unsigned sb_b = smem_u32(Sb), cb_b = smem_u32(Cb);
        if (tid < RU) K2s[tid] = g_K2[tid];
        for (int q = tid; q < 8*64; q += 128){
            int bb = q >> 6, i4 = (q & 63)*4;
            float4 v = *(const float4*)(X + (size_t)(b0+bb)*IN_D + i4);
            Xs[(i4+0)*9+bb]=v.x; Xs[(i4+1)*9+bb]=v.y;
            Xs[(i4+2)*9+bb]=v.z; Xs[(i4+3)*9+bb]=v.w;
        }
        auto issue = [&](int sc, int st){
            #pragma unroll
            for (int u = 0; u < 4; ++u){
                int q = tid + u*128;
                int rr = q >> 5, sg = q & 31;
                cpa16(sb_b + st*8192 + rr*512 + sg*16, g_S  + (size_t)(sc*16+rr)*RU + sg*4);
                cpa16(cb_b + st*8192 + rr*512 + sg*16, g_CS + (size_t)(sc*16+rr)*RU + sg*4);
            }
        };
        ull A1p[2][2], A2p[2][2];
        #pragma unroll
        for (int bi = 0; bi < 2; ++bi){
            A1p[bi][0]=0ull; A1p[bi][1]=0ull; A2p[bi][0]=0ull; A2p[bi][1]=0ull;
        }
        issue(0, 0); CPA_COMMIT();
        for (int sc = 0; sc < 16; ++sc){
            CPA_WAIT0();
            __syncthreads();
            if (sc + 1 < 16){ issue(sc+1, (sc+1)&1); CPA_COMMIT(); }
            const float* Ss = Sb + (sc&1)*2048;
            const float* Cs = Cb + (sc&1)*2048;
            #pragma unroll 4
            for (int k = 0; k < 16; ++k){
                int i = sc*16 + k;
                float x0 = Xs[i*9 + wg*2 + 0];
                float x1 = Xs[i*9 + wg*2 + 1];
                ull xx0 = pk2(x0*x0), xx1 = pk2(x1*x1);
                ull xp0 = pk2(x0),    xp1 = pk2(x1);
                #pragma unroll
                for (int jp = 0; jp < 2; ++jp){
                    ull s2 = *(const ull*)(Ss + k*RU + 2*lane + 64*jp);
                    ull c2 = *(const ull*)(Cs + k*RU + 2*lane + 64*jp);
                    fma2(A1p[0][jp], xx0, s2); fma2(A1p[1][jp], xx1, s2);
                    fma2(A2p[0][jp], xp0, c2); fma2(A2p[1][jp], xp1, c2);
                }
            }
        }
        #pragma unroll
        for (int bi = 0; bi < 2; ++bi){
            float sx = 0.f, sxx = 0.f;
            #pragma unroll
            for (int t = 0; t < 8; ++t){
                float x = Xs[(lane + 32*t)*9 + wg*2 + bi];
                sx += x; sxx += x*x;
            }
            #pragma unroll
            for (int off = 16; off; off >>= 1){
                sx  += __shfl_xor_sync(0xffffffffu, sx,  off);
                sxx += __shfl_xor_sync(0xffffffffu, sxx, off);
            }
            float lg[4], e[4];
            #pragma unroll
            for (int jp = 0; jp < 2; ++jp){
                float a1l,a1h,a2l,a2h;
                unpk(A1p[bi][jp], a1l, a1h);
                unpk(A2p[bi][jp], a2l, a2h);
                int r = 2*lane + 64*jp;
                lg[2*jp+0] = -(a1l - 2.f*a2l + K2s[r+0]) * (1.f/256.f);
                lg[2*jp+1] = -(a1h - 2.f*a2h + K2s[r+1]) * (1.f/256.f);
            }
            float m = fmaxf(fmaxf(lg[0],lg[1]), fmaxf(lg[2],lg[3]));
            #pragma unroll
            for (int off = 16; off; off >>= 1)
                m = fmaxf(m, __shfl_xor_sync(0xffffffffu, m, off));
            float se = 0.f, se2 = 0.f;
            #pragma unroll
            for (int j = 0; j < 4; ++j){ e[j] = __expf(lg[j]-m); se += e[j]; se2 += e[j]*e[j]; }
            #pragma unroll
            for (int off = 16; off; off >>= 1){
                se  += __shfl_xor_sync(0xffffffffu, se,  off);
                se2 += __shfl_xor_sync(0xffffffffu, se2, off);
            }
            float inv  = 1.f/se;
            float mu   = (sx + 1.f) * (1.f/(float)DDIM);
            float ef2  = se2*inv*inv*(sxx + 1.f) * (1.f/(float)DDIM);
            float rstd = rsqrtf(ef2 - mu*mu + LN_EPS_C);
            int b = b0 + wg*2 + bi;
            float fr = inv*rstd;
            #pragma unroll
            for (int jp = 0; jp < 2; ++jp){
                int r = 2*lane + 64*jp;
                g_fsT[(size_t)(r  )*NB + b] = e[2*jp+0]*fr;
                g_fsT[(size_t)(r+1)*NB + b] = e[2*jp+1]*fr;
            }
            if (lane == 0) g_c0[b] = -mu*rstd;
        }
    } else if (blk < 768){
        // ---- W slab: build g_Bh + G/Bc partials (+ tail at ic==7) ----
        float* gw = sm1;                 // [128][33]
        const int wb = blk - 256;
        const int ic = wb & 7, o = wb >> 3;
        const int lane = tid & 31, w = tid >> 5;
        const int i0 = ic*32;
        float sg = 0.f, sb = 0.f;
        #pragma unroll
        for (int u = 0; u < 8; ++u){
            int q = tid + u*128;
            int row = q >> 3, seg = q & 7;
            int d = row*256 + i0 + seg*4;
            const float* wp = W + (size_t)o*DDIM + d;
            float4 wv  = *(const float4*)wp;
            float4 gv4 = *(const float4*)(gamma + d);
            float4 bv4 = *(const float4*)(beta  + d);
            float g0 = gv4.x*wv.x, g1 = gv4.y*wv.y, g2 = gv4.z*wv.z, g3 = gv4.w*wv.w;
            float* gp = gw + row*33 + seg*4;
            gp[0]=g0; gp[1]=g1; gp[2]=g2; gp[3]=g3;
            sg += (g0+g1)+(g2+g3);
            sb += (bv4.x*wv.x + bv4.y*wv.y) + (bv4.z*wv.z + bv4.w*wv.w);
        }
        __syncthreads();
        #pragma unroll
        for (int u = 0; u < 16; ++u){
            int q = tid + u*128;
            int il = q >> 6, rp = q & 63;
            float a = gw[(2*rp  )*33 + il];
            float b = gw[(2*rp+1)*33 + il];
            g_Bh[(size_t)(i0+il)*4096 + o*64 + rp] = pack_h2(a, b);
        }
        #pragma unroll
        for (int off = 16; off; off >>= 1){
            sg += __shfl_down_sync(0xffffffffu, sg, off);
            sb += __shfl_down_sync(0xffffffffu, sb, off);
        }
        if (lane == 0){ rg[w] = sg; rb[w] = sb; }
        __syncthreads();
        if (tid == 0){
            g_Gp[o*9 + ic] = (rg[0]+rg[1])+(rg[2]+rg[3]);
            g_Bp[o*9 + ic] = (rb[0]+rb[1])+(rb[2]+rb[3]);
        }
        if (ic == 7){
            int d = 32768 + tid;
            float wv = W[(size_t)o*DDIM + d];
            float tgv = gamma[d]*wv;
            float tbv = beta[d]*wv;
            g_Wt[o*RU + tid] = tgv;
            #pragma unroll
            for (int off = 16; off; off >>= 1){
                tgv += __shfl_down_sync(0xffffffffu, tgv, off);
                tbv += __shfl_down_sync(0xffffffffu, tbv, off);
            }
            if (lane == 0){ trg[w] = tgv; trb[w] = tbv; }
            __syncthreads();
            if (tid == 0){
                g_Gp[o*9 + 8] = (trg[0]+trg[1])+(trg[2]+trg[3]);
                g_Bp[o*9 + 8] = (trb[0]+trb[1])+(trb[2]+trb[3]);
            }
        }
    } else {
        // ---- X pack ----
        int xb = blk - 768;
        #pragma unroll
        for (int u = 0; u < 16; ++u){
            int p = xb*2048 + tid + u*128;
            float2 x = *(const float2*)(X + 2*(size_t)p);
            g_Xh[p] = pack_h2(x.x, x.y);
        }
    }
}

// ---------------- launch 3: k2 — fp16 GEMM via ldmatrix/mma.sync, 4-stage cp.async ----------------
#define A_PITCH 80
#define B_PITCH 272
#define R_A  0u
#define R_B  10240u
#define BUF_SZ 18944u
#define OFF_RED 75776u
#define OFF_WT  76800u
#define OFF_GB  77312u
#define K2_SMEM 77376u

__global__ __launch_bounds__(256,2) void k2_mma(const float* __restrict__ bias,
                                                float* __restrict__ out){
    extern __shared__ __align__(16) char sm[];
    float* Wts = (float*)(sm + OFF_WT);
    float* Ps  = (float*)sm;
    float* Red = (float*)(sm + OFF_RED);
    float* GBs = (float*)(sm + OFF_GB);
    const unsigned base = smem_u32(sm);
    const int tid = threadIdx.x;
    const int b0  = blockIdx.x * 128;
    const int o   = blockIdx.y;
    const int w   = tid >> 5, lane = tid & 31;
    const int mw  = w >> 1, nw = w & 1;

    if (tid < 128) Wts[tid] = g_Wt[o*RU + tid];
    if (tid == 0){
        float g = 0.f, bc = 0.f;
        #pragma unroll
        for (int s = 0; s < 9; ++s){ g += g_Gp[o*9+s]; bc += g_Bp[o*9+s]; }
        GBs[0] = g; GBs[1] = bc;
    }

    auto issue = [&](int kc, unsigned bufb){
        {
            int q = tid;
            int row = q >> 2, s = q & 3;
            cpa16(bufb + R_A + row*A_PITCH + s*16, g_Xh + (size_t)(b0+row)*128 + kc*16 + s*4);
            q = tid + 256;
            row = q >> 2; s = q & 3;
            cpa16(bufb + R_A + row*A_PITCH + s*16, g_Xh + (size_t)(b0+row)*128 + kc*16 + s*4);
        }
        {
            int q = tid;
            int k = q >> 4, s = q & 15;
            cpa16(bufb + R_B + k*B_PITCH + s*16, g_Bh + (size_t)(kc*32+k)*4096 + o*64 + s*4);
            q = tid + 256;
            k = q >> 4; s = q & 15;
            cpa16(bufb + R_B + k*B_PITCH + s*16, g_Bh + (size_t)(kc*32+k)*4096 + o*64 + s*4);
        }
    };

    const unsigned arow = (unsigned)(mw*32) + (lane&7) + ((lane>>3)&1)*8;
    const unsigned aoff = arow*A_PITCH + ((lane>>4)*16);
    const unsigned krow = (lane&7) + ((lane>>3)&1)*8;
    const unsigned boff = krow*B_PITCH + (unsigned)nw*128 + ((lane>>4)*16);

    float acc[2][8][4];
    #pragma unroll
    for (int mt = 0; mt < 2; ++mt)
        #pragma unroll
        for (int nt = 0; nt < 8; ++nt)
            #pragma unroll
            for (int i = 0; i < 4; ++i) acc[mt][nt][i] = 0.f;

    issue(0, base); CPA_COMMIT();
    issue(1, base + BUF_SZ); CPA_COMMIT();
    issue(2, base + 2*BUF_SZ); CPA_COMMIT();
    for (int kc = 0; kc < 8; ++kc){
        if (kc <= 5)      CPA_WAIT2();
        else if (kc == 6) CPA_WAIT1();
        else              CPA_WAIT0();
        __syncthreads();
        if (kc + 3 < 8){ issue(kc+3, base + ((kc+3)&3)*BUF_SZ); CPA_COMMIT(); }
        const unsigned ab = base + (kc&3)*BUF_SZ + R_A + aoff;
        const unsigned bb = base + (kc&3)*BUF_SZ + R_B + boff;
        unsigned Af[2][2][4];
        unsigned Bf[2][8][2];
        ldm4(Af[0][0], ab);
        ldm4(Af[0][1], ab + 32);
        ldm4(Af[1][0], ab + 16*A_PITCH);
        ldm4(Af[1][1], ab + 16*A_PITCH + 32);
        #pragma unroll
        for (int ks = 0; ks < 2; ++ks)
            #pragma unroll
            for (int ntp = 0; ntp < 4; ++ntp)
                ldm4t(&Bf[ks][2*ntp][0], bb + ks*16*B_PITCH + ntp*32);
        #pragma unroll
        for (int ks = 0; ks < 2; ++ks)
            #pragma unroll
            for (int nt = 0; nt < 8; ++nt)
                #pragma unroll
                for (int mt = 0; mt < 2; ++mt)
                    mma16816(acc[mt][nt], Af[mt][ks], Bf[ks][nt]);
    }
    __syncthreads();
    {
        int r0 = mw*32 + (lane>>2);
        int c0 = nw*64 + (lane&3)*2;
        #pragma unroll
        for (int mt = 0; mt < 2; ++mt)
            #pragma unroll
            for (int nt = 0; nt < 8; ++nt){
                int r = r0 + mt*16, c = c0 + nt*8;
                Ps[r     + (c  )*132] = acc[mt][nt][0];
                Ps[r     + (c+1)*132] = acc[mt][nt][1];
                Ps[r + 8 + (c  )*132] = acc[mt][nt][2];
                Ps[r + 8 + (c+1)*132] = acc[mt][nt][3];
            }
    }
    __syncthreads();
    {
        int half = tid >> 7, bl = tid & 127;
        int b = b0 + bl;
        float s0 = 0.f, s1 = 0.f, s2 = 0.f, s3 = 0.f;
        int rb0 = half*64;
        #pragma unroll
        for (int u = 0; u < 16; ++u){
            int r = rb0 + 4*u;
            s0 += g_fsT[(size_t)(r  )*NB + b] * (Ps[bl + (r  )*132] + Wts[r  ]);
            s1 += g_fsT[(size_t)(r+1)*NB + b] * (Ps[bl + (r+1)*132] + Wts[r+1]);
            s2 += g_fsT[(size_t)(r+2)*NB + b] * (Ps[bl + (r+2)*132] + Wts[r+2]);
            s3 += g_fsT[(size_t)(r+3)*NB + b] * (Ps[bl + (r+3)*132] + Wts[r+3]);
        }
        Red[tid] = (s0+s1)+(s2+s3);
    }
    __syncthreads();
    if (tid < 128){
        int b = b0 + tid;
        float v = Red[tid] + Red[tid+128];
        out[(size_t)b*OD + o] = v + g_c0[b]*GBs[0] + GBs[1] + bias[o];
    }
}

// ---------------- launch ----------------
extern "C" void kernel_launch(void* const* d_in, const int* in_sizes, int n_in,
                              void* d_out, int out_size){
    const float* X       = (const float*)d_in[0];
    const float* centers = (const float*)d_in[1];
    const float* sigmas  = (const float*)d_in[2];
    const float* gamma   = (const float*)d_in[3];
    const float* beta    = (const float*)d_in[4];
    const float* W       = (const float*)d_in[5];
    const float* bias    = (const float*)d_in[6];
    float* out = (float*)d_out;
    (void)in_sizes; (void)n_in; (void)out_size;

    cudaFuncSetAttribute(k1w,    cudaFuncAttributeMaxDynamicSharedMemorySize, K1_SMEM);
    cudaFuncSetAttribute(k2_mma, cudaFuncAttributeMaxDynamicSharedMemorySize, K2_SMEM);

    k0s_prep <<<256, 256>>>(centers, sigmas);                       // 1 (~2us)
    k1w      <<<896, 128, K1_SMEM>>>(X, W, gamma, beta);            // 2 (k1 || k2-prep)
    k2_mma   <<<dim3(NB/128, OD), 256, K2_SMEM>>>(bias, out);       // 3
}

// round 17
// speedup vs baseline: 1.1411x; 1.1411x over previous
#include <cuda_runtime.h>
#include <cuda_fp16.h>

#define IN_D 256
#define RU   128
#define OD   64
#define NB   2048
#define DDIM 32896
#define HCONST 0.5f
#define EPS_C  1e-8f
#define LN_EPS_C 1e-5f

typedef unsigned long long ull;

// ---------------- device scratch (allocation-free) ----------------
__device__ float    g_S  [IN_D*RU];
__device__ float    g_CS [IN_D*RU];
__device__ float    g_K2 [RU];
__device__ float    g_Gp [OD*9];       // G partials  [o][slot], race-free
__device__ float    g_Bp [OD*9];       // Bc partials [o][slot]
__device__ float    g_fsT[RU*NB];      // (frs*rstd) transposed: [r][b]
__device__ float    g_c0 [NB];         // -mu*rstd
__device__ float    g_Wt [OD*RU];      // tail weights gamma*W[o][32768+r]
__device__ unsigned g_Bh [256*4096];   // B fp16 [i=256][n_w=4096] f16x2, n_w = o*64 + r/2
__device__ unsigned g_Xh [NB*128];     // X fp16 [b][128 words]

// ---------------- helpers ----------------
__device__ __forceinline__ ull pk2(float x){
    unsigned u = __float_as_uint(x);
    ull r; asm("mov.b64 %0, {%1, %1};" : "=l"(r) : "r"(u)); return r;
}
__device__ __forceinline__ void fma2(ull &d, ull a, ull b){
    asm("fma.rn.f32x2 %0, %1, %2, %0;" : "+l"(d) : "l"(a), "l"(b));
}
__device__ __forceinline__ void unpk(ull v, float &lo, float &hi){
    unsigned ulo, uhi;
    asm("mov.b64 {%0, %1}, %2;" : "=r"(ulo), "=r"(uhi) : "l"(v));
    lo = __uint_as_float(ulo); hi = __uint_as_float(uhi);
}
__device__ __forceinline__ unsigned pack_h2(float a, float b){
    unsigned h; asm("cvt.rn.f16x2.f32 %0, %1, %2;" : "=r"(h) : "f"(b), "f"(a));
    return h;
}
__device__ __forceinline__ unsigned smem_u32(const void* p){
    unsigned a;
    asm("{ .reg .u64 t; cvta.to.shared.u64 t, %1; cvt.u32.u64 %0, t; }" : "=r"(a) : "l"(p));
    return a;
}
__device__ __forceinline__ void cpa16(unsigned dst, const void* src){
    asm volatile("cp.async.cg.shared.global [%0], [%1], 16;" :: "r"(dst), "l"(src) : "memory");
}
#define CPA_COMMIT() asm volatile("cp.async.commit_group;" ::: "memory")
#define CPA_WAIT2()  asm volatile("cp.async.wait_group 2;" ::: "memory")
#define CPA_WAIT1()  asm volatile("cp.async.wait_group 1;" ::: "memory")
#define CPA_WAIT0()  asm volatile("cp.async.wait_group 0;" ::: "memory")

__device__ __forceinline__ void ldm4(unsigned* r, unsigned addr){
    asm volatile("ldmatrix.sync.aligned.m8n8.x4.shared.b16 {%0,%1,%2,%3}, [%4];"
        : "=r"(r[0]), "=r"(r[1]), "=r"(r[2]), "=r"(r[3]) : "r"(addr));
}
__device__ __forceinline__ void ldm4t(unsigned* r, unsigned addr){
    asm volatile("ldmatrix.sync.aligned.m8n8.x4.trans.shared.b16 {%0,%1,%2,%3}, [%4];"
        : "=r"(r[0]), "=r"(r[1]), "=r"(r[2]), "=r"(r[3]) : "r"(addr));
}
__device__ __forceinline__ void mma16816(float* d, const unsigned* a, const unsigned* b){
    asm volatile("mma.sync.aligned.m16n8k16.row.col.f32.f16.f16.f32 "
        "{%0,%1,%2,%3}, {%4,%5,%6,%7}, {%8,%9}, {%0,%1,%2,%3};"
        : "+f"(d[0]), "+f"(d[1]), "+f"(d[2]), "+f"(d[3])
        : "r"(a[0]), "r"(a[1]), "r"(a[2]), "r"(a[3]), "r"(b[0]), "r"(b[1]));
}

// ---------------- launch 1: k0_fused — B build(vec4) + tail + X pack(MLP8) + rule consts + K2 ----------------
// blocks [0,512): bsplit; [512,640): X pack (8 pairs/thr) + S/CS; [640,768): K2.
__global__ void k0_fused(const float* __restrict__ W, const float* __restrict__ gamma,
                         const float* __restrict__ beta,
                         const float* __restrict__ centers, const float* __restrict__ sigmas,
                         const float* __restrict__ X){
    __shared__ float gw[128*33];
    __shared__ float rg[8], rb[8], trg[4], trb[4];
    __shared__ float red[256];
    const int t = threadIdx.x, blk = blockIdx.x;
    if (blk < 512){
        const int ic = blk & 7, o = blk >> 3;
        const int lane = t & 31, w = t >> 5;
        const int i0 = ic*32;
        float sg = 0.f, sb = 0.f;
        // vectorized: thread handles (row = q>>3, seg = q&7) -> 4 floats, 4 iters
        #pragma unroll
        for (int u = 0; u < 4; ++u){
            int q = t + u*256;
            int row = q >> 3, seg = q & 7;
            int d = row*256 + i0 + seg*4;
            float4 wv  = *(const float4*)(W + (size_t)o*DDIM + d);
            float4 gv4 = *(const float4*)(gamma + d);
            float4 bv4 = *(const float4*)(beta  + d);
            float g0 = gv4.x*wv.x, g1 = gv4.y*wv.y, g2 = gv4.z*wv.z, g3 = gv4.w*wv.w;
            float* gp = gw + row*33 + seg*4;
            gp[0]=g0; gp[1]=g1; gp[2]=g2; gp[3]=g3;
            sg += (g0+g1)+(g2+g3);
            sb += (bv4.x*wv.x + bv4.y*wv.y) + (bv4.z*wv.z + bv4.w*wv.w);
        }
        __syncthreads();
        #pragma unroll
        for (int u = 0; u < 8; ++u){
            int q = t + u*256;
            int il = q >> 6, rp = q & 63;
            float a = gw[(2*rp  )*33 + il];
            float b = gw[(2*rp+1)*33 + il];
            g_Bh[(size_t)(i0+il)*4096 + o*64 + rp] = pack_h2(a, b);
        }
        #pragma unroll
        for (int off = 16; off; off >>= 1){
            sg += __shfl_down_sync(0xffffffffu, sg, off);
            sb += __shfl_down_sync(0xffffffffu, sb, off);
        }
        if (lane == 0){ rg[w] = sg; rb[w] = sb; }
        __syncthreads();
        if (t == 0){
            float a = 0.f, b2 = 0.f;
            #pragma unroll
            for (int u = 0; u < 8; ++u){ a += rg[u]; b2 += rb[u]; }
            g_Gp[o*9 + ic] = a; g_Bp[o*9 + ic] = b2;
        }
        if (ic == 7){
            float tgv = 0.f, tbv = 0.f;
            if (t < 128){
                int d = 32768 + t;
                float wv = W[(size_t)o*DDIM + d];
                tgv = gamma[d]*wv;
                tbv = beta[d]*wv;
                g_Wt[o*RU + t] = tgv;
            }
            #pragma unroll
            for (int off = 16; off; off >>= 1){
                tgv += __shfl_down_sync(0xffffffffu, tgv, off);
                tbv += __shfl_down_sync(0xffffffffu, tbv, off);
            }
            if (lane == 0 && t < 128){ trg[w] = tgv; trb[w] = tbv; }
            __syncthreads();
            if (t == 0){
                g_Gp[o*9 + 8] = trg[0]+trg[1]+trg[2]+trg[3];
                g_Bp[o*9 + 8] = trb[0]+trb[1]+trb[2]+trb[3];
            }
        }
    } else if (blk < 640){
        int b2 = blk - 512;
        #pragma unroll
        for (int u = 0; u < 8; ++u){
            int p = b2*2048 + t + u*256;
            float2 x = *(const float2*)(X + 2*(size_t)p);
            g_Xh[p] = pack_h2(x.x, x.y);
        }
        int i = b2*256 + t;
        float sg = sigmas[i];
        float s  = HCONST/(sg*sg) + EPS_C;
        g_S[i]  = s;
        g_CS[i] = centers[i]*s;
    } else {
        int r = blk - 640;
        float c = centers[t*RU + r], sg = sigmas[t*RU + r];
        float s = HCONST/(sg*sg) + EPS_C;
        red[t] = c*c*s;
        __syncthreads();
        for (int s2 = 128; s2 > 0; s2 >>= 1){
            if (t < s2) red[t] += red[t+s2];
            __syncthreads();
        }
        if (t == 0) g_K2[r] = red[0];
    }
}

// ---------------- launch 2: k1 — firing levels + softmax + LN stats (cp.async S/C tiles) ----------------
#define K1_SMEM 41984
__global__ __launch_bounds__(128,4) void k1_frs(const float* __restrict__ X){
    extern __shared__ float sm1[];
    float* Xs = sm1;                 // [256][9]
    float* Sb = sm1 + 2304;          // 2 stages x [16][128]
    float* Cb = Sb  + 4096;
    __shared__ float K2s[RU];
    const int tid  = threadIdx.x;
    const int b0   = blockIdx.x * 8;
    const int lane = tid & 31, wg = tid >> 5;
    const unsigned sb_b = smem_u32(Sb), cb_b = smem_u32(Cb);
    if (tid < RU) K2s[tid] = g_K2[tid];
    for (int q = tid; q < 8*64; q += 128){
        int bb = q >> 6, i4 = (q & 63)*4;
        float4 v = *(const float4*)(X + (size_t)(b0+bb)*IN_D + i4);
        Xs[(i4+0)*9+bb]=v.x; Xs[(i4+1)*9+bb]=v.y;
        Xs[(i4+2)*9+bb]=v.z; Xs[(i4+3)*9+bb]=v.w;
    }
    auto issue = [&](int sc, int st){
        #pragma unroll
        for (int u = 0; u < 4; ++u){
            int q = tid + u*128;
            int rr = q >> 5, sg = q & 31;
            cpa16(sb_b + st*8192 + rr*512 + sg*16, g_S  + (size_t)(sc*16+rr)*RU + sg*4);
            cpa16(cb_b + st*8192 + rr*512 + sg*16, g_CS + (size_t)(sc*16+rr)*RU + sg*4);
        }
    };
    ull A1p[2][2], A2p[2][2];
    #pragma unroll
    for (int bi = 0; bi < 2; ++bi){
        A1p[bi][0]=0ull; A1p[bi][1]=0ull; A2p[bi][0]=0ull; A2p[bi][1]=0ull;
    }
    issue(0, 0); CPA_COMMIT();
    for (int sc = 0; sc < 16; ++sc){
        CPA_WAIT0();
        __syncthreads();
        if (sc + 1 < 16){ issue(sc+1, (sc+1)&1); CPA_COMMIT(); }
        const float* Ss = Sb + (sc&1)*2048;
        const float* Cs = Cb + (sc&1)*2048;
        #pragma unroll 4
        for (int k = 0; k < 16; ++k){
            int i = sc*16 + k;
            float x0 = Xs[i*9 + wg*2 + 0];
            float x1 = Xs[i*9 + wg*2 + 1];
            ull xx0 = pk2(x0*x0), xx1 = pk2(x1*x1);
            ull xp0 = pk2(x0),    xp1 = pk2(x1);
            #pragma unroll
            for (int jp = 0; jp < 2; ++jp){
                ull s2 = *(const ull*)(Ss + k*RU + 2*lane + 64*jp);
                ull c2 = *(const ull*)(Cs + k*RU + 2*lane + 64*jp);
                fma2(A1p[0][jp], xx0, s2); fma2(A1p[1][jp], xx1, s2);
                fma2(A2p[0][jp], xp0, c2); fma2(A2p[1][jp], xp1, c2);
            }
        }
    }
    #pragma unroll
    for (int bi = 0; bi < 2; ++bi){
        float sx = 0.f, sxx = 0.f;
        #pragma unroll
        for (int t = 0; t < 8; ++t){
            float x = Xs[(lane + 32*t)*9 + wg*2 + bi];
            sx += x; sxx += x*x;
        }
        #pragma unroll
        for (int off = 16; off; off >>= 1){
            sx  += __shfl_xor_sync(0xffffffffu, sx,  off);
            sxx += __shfl_xor_sync(0xffffffffu, sxx, off);
        }
        float lg[4], e[4];
        #pragma unroll
        for (int jp = 0; jp < 2; ++jp){
            float a1l,a1h,a2l,a2h;
            unpk(A1p[bi][jp], a1l, a1h);
            unpk(A2p[bi][jp], a2l, a2h);
            int r = 2*lane + 64*jp;
            lg[2*jp+0] = -(a1l - 2.f*a2l + K2s[r+0]) * (1.f/256.f);
            lg[2*jp+1] = -(a1h - 2.f*a2h + K2s[r+1]) * (1.f/256.f);
        }
        float m = fmaxf(fmaxf(lg[0],lg[1]), fmaxf(lg[2],lg[3]));
        #pragma unroll
        for (int off = 16; off; off >>= 1)
            m = fmaxf(m, __shfl_xor_sync(0xffffffffu, m, off));
        float se = 0.f, se2 = 0.f;
        #pragma unroll
        for (int j = 0; j < 4; ++j){ e[j] = __expf(lg[j]-m); se += e[j]; se2 += e[j]*e[j]; }
        #pragma unroll
        for (int off = 16; off; off >>= 1){
            se  += __shfl_xor_sync(0xffffffffu, se,  off);
            se2 += __shfl_xor_sync(0xffffffffu, se2, off);
        }
        float inv  = 1.f/se;
        float mu   = (sx + 1.f) * (1.f/(float)DDIM);
        float ef2  = se2*inv*inv*(sxx + 1.f) * (1.f/(float)DDIM);
        float rstd = rsqrtf(ef2 - mu*mu + LN_EPS_C);
        int b = b0 + wg*2 + bi;
        float fr = inv*rstd;
        #pragma unroll
        for (int jp = 0; jp < 2; ++jp){
            int r = 2*lane + 64*jp;
            g_fsT[(size_t)(r  )*NB + b] = e[2*jp+0]*fr;
            g_fsT[(size_t)(r+1)*NB + b] = e[2*jp+1]*fr;
        }
        if (lane == 0) g_c0[b] = -mu*rstd;
    }
}

// ---------------- launch 3: k2 — fp16 GEMM via ldmatrix/mma.sync, 4-stage cp.async ----------------
#define A_PITCH 80
#define B_PITCH 272
#define R_A  0u
#define R_B  10240u
#define BUF_SZ 18944u
#define OFF_RED 75776u
#define OFF_WT  76800u
#define OFF_GB  77312u
#define K2_SMEM 77376u

__global__ __launch_bounds__(256,2) void k2_mma(const float* __restrict__ bias,
                                                float* __restrict__ out){
    extern __shared__ __align__(16) char sm[];
    float* Wts = (float*)(sm + OFF_WT);
    float* Ps  = (float*)sm;
    float* Red = (float*)(sm + OFF_RED);
    float* GBs = (float*)(sm + OFF_GB);
    const unsigned base = smem_u32(sm);
    const int tid = threadIdx.x;
    const int b0  = blockIdx.x * 128;
    const int o   = blockIdx.y;
    const int w   = tid >> 5, lane = tid & 31;
    const int mw  = w >> 1, nw = w & 1;

    if (tid < 128) Wts[tid] = g_Wt[o*RU + tid];
    if (tid == 0){
        float g = 0.f, bc = 0.f;
        #pragma unroll
        for (int s = 0; s < 9; ++s){ g += g_Gp[o*9+s]; bc += g_Bp[o*9+s]; }
        GBs[0] = g; GBs[1] = bc;
    }

    auto issue = [&](int kc, unsigned bufb){
        {
            int q = tid;
            int row = q >> 2, s = q & 3;
            cpa16(bufb + R_A + row*A_PITCH + s*16, g_Xh + (size_t)(b0+row)*128 + kc*16 + s*4);
            q = tid + 256;
            row = q >> 2; s = q & 3;
            cpa16(bufb + R_A + row*A_PITCH + s*16, g_Xh + (size_t)(b0+row)*128 + kc*16 + s*4);
        }
        {
            int q = tid;
            int k = q >> 4, s = q & 15;
            cpa16(bufb + R_B + k*B_PITCH + s*16, g_Bh + (size_t)(kc*32+k)*4096 + o*64 + s*4);
            q = tid + 256;
            k = q >> 4; s = q & 15;
            cpa16(bufb + R_B + k*B_PITCH + s*16, g_Bh + (size_t)(kc*32+k)*4096 + o*64 + s*4);
        }
    };

    const unsigned arow = (unsigned)(mw*32) + (lane&7) + ((lane>>3)&1)*8;
    const unsigned aoff = arow*A_PITCH + ((lane>>4)*16);
    const unsigned krow = (lane&7) + ((lane>>3)&1)*8;
    const unsigned boff = krow*B_PITCH + (unsigned)nw*128 + ((lane>>4)*16);

    float acc[2][8][4];
    #pragma unroll
    for (int mt = 0; mt < 2; ++mt)
        #pragma unroll
        for (int nt = 0; nt < 8; ++nt)
            #pragma unroll
            for (int i = 0; i < 4; ++i) acc[mt][nt][i] = 0.f;

    issue(0, base); CPA_COMMIT();
    issue(1, base + BUF_SZ); CPA_COMMIT();
    issue(2, base + 2*BUF_SZ); CPA_COMMIT();
    for (int kc = 0; kc < 8; ++kc){
        if (kc <= 5)      CPA_WAIT2();
        else if (kc == 6) CPA_WAIT1();
        else              CPA_WAIT0();
        __syncthreads();
        if (kc + 3 < 8){ issue(kc+3, base + ((kc+3)&3)*BUF_SZ); CPA_COMMIT(); }
        const unsigned ab = base + (kc&3)*BUF_SZ + R_A + aoff;
        const unsigned bb = base + (kc&3)*BUF_SZ + R_B + boff;
        unsigned Af[2][2][4];
        unsigned Bf[2][8][2];
        ldm4(Af[0][0], ab);
        ldm4(Af[0][1], ab + 32);
        ldm4(Af[1][0], ab + 16*A_PITCH);
        ldm4(Af[1][1], ab + 16*A_PITCH + 32);
        #pragma unroll
        for (int ks = 0; ks < 2; ++ks)
            #pragma unroll
            for (int ntp = 0; ntp < 4; ++ntp)
                ldm4t(&Bf[ks][2*ntp][0], bb + ks*16*B_PITCH + ntp*32);
        #pragma unroll
        for (int ks = 0; ks < 2; ++ks)
            #pragma unroll
            for (int nt = 0; nt < 8; ++nt)
                #pragma unroll
                for (int mt = 0; mt < 2; ++mt)
                    mma16816(acc[mt][nt], Af[mt][ks], Bf[ks][nt]);
    }
    __syncthreads();
    {
        int r0 = mw*32 + (lane>>2);
        int c0 = nw*64 + (lane&3)*2;
        #pragma unroll
        for (int mt = 0; mt < 2; ++mt)
            #pragma unroll
            for (int nt = 0; nt < 8; ++nt){
                int r = r0 + mt*16, c = c0 + nt*8;
                Ps[r     + (c  )*132] = acc[mt][nt][0];
                Ps[r     + (c+1)*132] = acc[mt][nt][1];
                Ps[r + 8 + (c  )*132] = acc[mt][nt][2];
                Ps[r + 8 + (c+1)*132] = acc[mt][nt][3];
            }
    }
    __syncthreads();
    {
        int half = tid >> 7, bl = tid & 127;
        int b = b0 + bl;
        float s0 = 0.f, s1 = 0.f, s2 = 0.f, s3 = 0.f;
        int rb0 = half*64;
        #pragma unroll
        for (int u = 0; u < 16; ++u){
            int r = rb0 + 4*u;
            s0 += g_fsT[(size_t)(r  )*NB + b] * (Ps[bl + (r  )*132] + Wts[r  ]);
            s1 += g_fsT[(size_t)(r+1)*NB + b] * (Ps[bl + (r+1)*132] + Wts[r+1]);
            s2 += g_fsT[(size_t)(r+2)*NB + b] * (Ps[bl + (r+2)*132] + Wts[r+2]);
            s3 += g_fsT[(size_t)(r+3)*NB + b] * (Ps[bl + (r+3)*132] + Wts[r+3]);
        }
        Red[tid] = (s0+s1)+(s2+s3);
    }
    __syncthreads();
    if (tid < 128){
        int b = b0 + tid;
        float v = Red[tid] + Red[tid+128];
        out[(size_t)b*OD + o] = v + g_c0[b]*GBs[0] + GBs[1] + bias[o];
    }
}

// ---------------- launch ----------------
extern "C" void kernel_launch(void* const* d_in, const int* in_sizes, int n_in,
                              void* d_out, int out_size){
    const float* X       = (const float*)d_in[0];
    const float* centers = (const float*)d_in[1];
    const float* sigmas  = (const float*)d_in[2];
    const float* gamma   = (const float*)d_in[3];
    const float* beta    = (const float*)d_in[4];
    const float* W       = (const float*)d_in[5];
    const float* bias    = (const float*)d_in[6];
    float* out = (float*)d_out;
    (void)in_sizes; (void)n_in; (void)out_size;

    cudaFuncSetAttribute(k1_frs, cudaFuncAttributeMaxDynamicSharedMemorySize, K1_SMEM);
    cudaFuncSetAttribute(k2_mma, cudaFuncAttributeMaxDynamicSharedMemorySize, K2_SMEM);

    k0_fused <<<768, 256>>>(W, gamma, beta, centers, sigmas, X);    // 1
    k1_frs   <<<NB/8, 128, K1_SMEM>>>(X);                           // 2
    k2_mma   <<<dim3(NB/128, OD), 256, K2_SMEM>>>(bias, out);       // 3
}